// round 15
// baseline (speedup 1.0000x reference)
#include <cuda_runtime.h>
#include <cuda_bf16.h>
#include <math.h>
#include <stdint.h>

#define D 256
#define HW 4096
#define NQ 300
#define NP 8
#define KP1 2304
#define NLAY 6

typedef __nv_bfloat16 bf16;

// plane strides
#define S_XIN ((long long)2 * HW * 512)
#define S_Y   ((long long)2 * HW * 256)
#define S_FLAT ((long long)2 * NQ * NP * KP1)
#define S_Q   ((long long)2 * NQ * 256)
#define S_W2  ((long long)256 * 512)
#define S_WT  ((long long)256 * KP1)
#define S_WP1 ((long long)NLAY * 256 * KP1)
#define S_WBIG ((long long)NLAY * 768 * 256)
#define S_WCT ((long long)512 * 256)
#define S_WLAT ((long long)256 * 256)
#define S_COEF ((long long)512 * 128)
#define S_WIN  ((long long)256 * 128)
#define S_VAL  ((long long)128 * 256)

// ---------------- scratch (device globals; no allocation) ----------------
__device__ float g_b2v[D];
__device__ float g_pos[128 * 256];
__device__ float g_bbig[NLAY * 768];
__device__ float g_bo2[NLAY * 256];
__device__ float g_WoP[NLAY * 256 * 256];
__device__ bf16 g_coeffs[2 * S_COEF];
__device__ bf16 g_w_ins[2 * S_WIN];
__device__ bf16 g_vals[2 * S_VAL];
__device__ bf16 g_WcTs[2 * S_WCT];
__device__ bf16 g_wlats[2 * S_WLAT];
__device__ bf16 g_W2s[2 * S_W2];
__device__ bf16 g_wts[2 * S_WT];
__device__ bf16 g_Wp1s[2 * S_WP1];
__device__ bf16 g_wbigs[2 * S_WBIG];
__device__ bf16 g_xins[2 * S_XIN];
__device__ bf16 g_ys[2 * S_Y];
__device__ bf16 g_flats[2 * S_FLAT];
__device__ bf16 g_qs[2 * S_Q];
__device__ float g_f0[2 * HW * D];
__device__ float g_q[2 * NQ * D];
__device__ float g_big[2 * NQ * 768];
__device__ float g_kv[2 * NQ * D];
__device__ float g_boxes[2 * NQ * 4];

__device__ __forceinline__ void wsplit(bf16* h, bf16* l, float v) {
    bf16 hh = __float2bfloat16(v);
    *h = hh;
    *l = __float2bfloat16(v - __bfloat162float(hh));
}
__device__ __forceinline__ uint32_t pack2(float x, float y) {
    __nv_bfloat162 t = __floats2bfloat162_rn(x, y);
    return *(uint32_t*)&t;
}

__device__ __forceinline__ void mma_bf16(float* c, const uint32_t* a, const uint32_t* b) {
    asm volatile(
        "mma.sync.aligned.m16n8k16.row.col.f32.bf16.bf16.f32 "
        "{%0,%1,%2,%3},{%4,%5,%6,%7},{%8,%9},{%0,%1,%2,%3};"
        : "+f"(c[0]), "+f"(c[1]), "+f"(c[2]), "+f"(c[3])
        : "r"(a[0]), "r"(a[1]), "r"(a[2]), "r"(a[3]), "r"(b[0]), "r"(b[1]));
}

__device__ __forceinline__ void ldm4(uint32_t* r, const void* p) {
    uint32_t a = (uint32_t)__cvta_generic_to_shared(p);
    asm volatile("ldmatrix.sync.aligned.m8n8.x4.shared.b16 {%0,%1,%2,%3}, [%4];"
                 : "=r"(r[0]), "=r"(r[1]), "=r"(r[2]), "=r"(r[3]) : "r"(a));
}

__device__ __forceinline__ void cp16(void* dst, const void* src, int bytes) {
    uint32_t d = (uint32_t)__cvta_generic_to_shared(dst);
    asm volatile("cp.async.ca.shared.global [%0], [%1], 16, %2;\n" ::"r"(d), "l"(src), "r"(bytes));
}
__device__ __forceinline__ void cp_commit() { asm volatile("cp.async.commit_group;\n"); }
template <int N>
__device__ __forceinline__ void cp_waitN() { asm volatile("cp.async.wait_group %0;\n" ::"n"(N)); }

// ---------------- GEMM descriptor + shared body ----------------
struct GD {
    const bf16* A; long long sA;
    const bf16* W; long long sW;
    const float* bias; float* C; int ldc;
    bf16* OS; long long sOS;
    int M, N, K, act, accum, mode, pos, epi;
};

template <int MT, int NS>
__device__ __forceinline__ void gemm_body(const GD& d, int bx, int by) {
    constexpr int MSUB = MT / 4;
    constexpr int NMT = MT / 64;
    __shared__ uint32_t sAh[NS][MT][12], sAl[NS][MT][12];
    __shared__ uint32_t sBh[NS][64][12], sBl[NS][64][12];
    int m0 = bx * MT, n0 = by * 64;
    int tid = threadIdx.x;
    int warp = tid >> 5, lane = tid & 31;
    int wm = warp >> 1, wn = warp & 1;
    int g = lane >> 2, r = lane & 3;
    int lrow = lane & 15, lcol = (lane >> 4) * 4;
    float acc[NMT][4][4] = {};
    int nk = d.K >> 4;

    auto load = [&](int s, int k0) {
        if (MT == 128) {
            int row = tid >> 1, ch = tid & 1;
            int m = m0 + row;
            long long off = 0;
            int bytes = 0;
            if (d.mode == 0) {
                if (m < d.M) { off = (long long)m * d.K + k0 + ch * 8; bytes = 16; }
            } else {
                int tap = k0 >> 8;
                int dy = tap / 3 - 1, dx = tap % 3 - 1;
                int h = (m >> 6) & 63, w = m & 63;
                int hh = h + dy, ww = w + dx;
                if (m < d.M && (unsigned)hh < 64u && (unsigned)ww < 64u) {
                    off = (long long)(m + dy * 64 + dx) * 256 + (k0 & 255) + ch * 8;
                    bytes = 16;
                }
            }
            cp16(&sAh[s][row][ch * 4], d.A + off, bytes);
            cp16(&sAl[s][row][ch * 4], d.A + d.sA + off, bytes);
        } else {
            int p = tid >> 7;
            int row = (tid >> 1) & 63, ch = tid & 1;
            int m = m0 + row;
            long long off = 0;
            int bytes = 0;
            if (m < d.M) { off = (long long)m * d.K + k0 + ch * 8; bytes = 16; }
            if (p) cp16(&sAl[s][row][ch * 4], d.A + d.sA + off, bytes);
            else   cp16(&sAh[s][row][ch * 4], d.A + off, bytes);
        }
        {
            int p = tid >> 7;
            int row = (tid >> 1) & 63, ch = tid & 1;
            int n = n0 + row;
            const bf16* src = d.W;
            int bytes = 0;
            if (n < d.N) {
                src = d.W + (long long)p * d.sW + (long long)n * d.K + k0 + ch * 8;
                bytes = 16;
            }
            if (p) cp16(&sBl[s][row][ch * 4], src, bytes);
            else   cp16(&sBh[s][row][ch * 4], src, bytes);
        }
        cp_commit();
    };

#pragma unroll
    for (int s = 0; s < NS - 1; s++) {
        if (s < nk) load(s, s << 4);
        else cp_commit();
    }
    for (int kt = 0; kt < nk; kt++) {
        int cur = kt % NS;
        cp_waitN<NS - 2>();
        __syncthreads();
        if (kt + NS - 1 < nk) load((kt + NS - 1) % NS, (kt + NS - 1) << 4);
        else cp_commit();
        uint32_t ah[NMT][4], al[NMT][4], bh[4][2], bl[4][2];
#pragma unroll
        for (int mt = 0; mt < NMT; mt++) {
            int rb = wm * MSUB + mt * 16;
            ldm4(ah[mt], &sAh[cur][rb + lrow][lcol]);
            ldm4(al[mt], &sAl[cur][rb + lrow][lcol]);
        }
#pragma unroll
        for (int np = 0; np < 2; np++) {
            int cb = wn * 32 + np * 16;
            uint32_t t[4];
            ldm4(t, &sBh[cur][cb + lrow][lcol]);
            bh[2 * np][0] = t[0]; bh[2 * np + 1][0] = t[1];
            bh[2 * np][1] = t[2]; bh[2 * np + 1][1] = t[3];
            ldm4(t, &sBl[cur][cb + lrow][lcol]);
            bl[2 * np][0] = t[0]; bl[2 * np + 1][0] = t[1];
            bl[2 * np][1] = t[2]; bl[2 * np + 1][1] = t[3];
        }
#pragma unroll
        for (int mt = 0; mt < NMT; mt++)
#pragma unroll
            for (int nt = 0; nt < 4; nt++) {
                mma_bf16(acc[mt][nt], ah[mt], bh[nt]);
                mma_bf16(acc[mt][nt], al[mt], bh[nt]);
                mma_bf16(acc[mt][nt], ah[mt], bl[nt]);
            }
    }

    if (d.epi == 1) {
#pragma unroll
        for (int mt = 0; mt < NMT; mt++) {
            int rbase = m0 + wm * MSUB + mt * 16;
#pragma unroll
            for (int nt = 0; nt < 4; nt++) {
                int n = n0 + wn * 32 + nt * 8 + 2 * r;
#pragma unroll
                for (int e = 0; e < 4; e++) {
                    int nn = n + (e & 1);
                    float v = fmaxf(acc[mt][nt][e] + d.bias[nn], 0.f);
                    v += __shfl_xor_sync(0xffffffffu, v, 4);
                    v += __shfl_xor_sync(0xffffffffu, v, 8);
                    v += __shfl_xor_sync(0xffffffffu, v, 16);
                    if (g == 0) {
                        int q = (rbase >> 3) + ((e >= 2) ? 1 : 0);
                        if (q < 2 * NQ) d.C[(long long)q * 256 + nn] = v * 0.125f;
                    }
                }
            }
        }
        return;
    }
#pragma unroll
    for (int mt = 0; mt < NMT; mt++) {
        int rbase = m0 + wm * MSUB + mt * 16;
#pragma unroll
        for (int nt = 0; nt < 4; nt++) {
            int cbase = n0 + wn * 32 + nt * 8 + 2 * r;
#pragma unroll
            for (int e = 0; e < 4; e++) {
                int m = rbase + g + ((e >= 2) ? 8 : 0);
                int n = cbase + (e & 1);
                if (m < d.M && n < d.N) {
                    float v = acc[mt][nt][e];
                    if (d.bias) v += d.bias[n];
                    if (d.act == 1 || (d.act == 2 && n < 512) || (d.act == 3 && n < 256))
                        v = fmaxf(v, 0.f);
                    if (d.pos) {
                        int hw = m & 4095;
                        v += g_pos[(hw >> 6) * 256 + n] + g_pos[16384 + (hw & 63) * 256 + n]
                           + g_b2v[n];
                    }
                    if (d.epi == 3) {
                        long long o = (long long)m * d.N + n;
                        wsplit(d.OS + o, d.OS + d.sOS + o, v);
                    } else {
                        if (d.accum) v += d.C[(long long)m * d.ldc + n];
                        d.C[(long long)m * d.ldc + n] = v;
                    }
                }
            }
        }
    }
}

template <int MT, int NS>
__global__ void __launch_bounds__(256, 2) tc_gemm3(GD d) {
    gemm_body<MT, NS>(d, blockIdx.x, blockIdx.y);
}

template <int MT, int NS>
__global__ void __launch_bounds__(256, 2) tc_gemm3_b3(GD d0, GD d1, GD d2) {
    GD d = (blockIdx.z == 0) ? d0 : ((blockIdx.z == 1) ? d1 : d2);
    if (blockIdx.x * MT >= d.M || (int)blockIdx.y * 64 >= d.N) return;
    gemm_body<MT, NS>(d, blockIdx.x, blockIdx.y);
}

// ---------------- MEGA-PREP (R14 blocks + transpose merged in) ----------------
#define B0 256
#define B0C 128
#define B1 128
#define B2 2304
#define B3 3072
#define B3B 12
#define B4 14080
#define B5 768
#define B6 13
#define B7 600
#define BT 4096
#define NBLK (B0 + B0C + B1 + B2 + B3 + B3B + B4 + B5 + B6 + B7 + BT)

__global__ void megaprep(
    const float* __restrict__ w_tf, const float* __restrict__ b_tf,
    const float* __restrict__ w_in, const float* __restrict__ b_in,
    const float* __restrict__ w_sm,
    const float* __restrict__ w_b1, const float* __restrict__ b_b1,
    const float* __restrict__ w_r1, const float* __restrict__ b_r1,
    const float* __restrict__ Wp1, const float* __restrict__ w_lat,
    const float* __restrict__ Wp2, const float* __restrict__ Wq,
    const float* __restrict__ Wo,
    const float* __restrict__ bq, const float* __restrict__ bp2,
    const float* __restrict__ bo, const float* __restrict__ b_lat,
    const float* __restrict__ qe, const float* __restrict__ qp,
    const float* __restrict__ pbi, const float* __restrict__ feat) {
    __shared__ float As[32][33], Bs[32][33];
    int bb = blockIdx.x;
    int tid = threadIdx.x;

    if (bb < B0) {
        int idx = bb * 256 + tid;
        int row = idx >> 7, c = idx & 127;
        int s = row >> 7, i = row & 127;
        const float* w3 = w_tf + (c * 128 + i) * 3;
        float coeff;
        if (s == 0)      coeff = w3[0] + w3[1];
        else if (s == 3) coeff = w3[1] + w3[2];
        else             coeff = w3[0] + w3[1] + w3[2];
        wsplit(g_coeffs + idx, g_coeffs + S_COEF + idx, 0.25f * coeff);
        return;
    }
    bb -= B0;
    if (bb < B0C) {
        int idx = bb * 256 + tid;
        wsplit(g_w_ins + idx, g_w_ins + S_WIN + idx, w_in[idx]);
        return;
    }
    bb -= B0C;
    if (bb < B1) {
        int idx = bb * 256 + tid;
        int m = idx >> 8, c = idx & 255;
        float v = 0.f;
        int h = m & 63;
        bool lowhalf = (m < 64);
        int cc = lowhalf ? c : c - 128;
        if ((lowhalf && c < 128) || (!lowhalf && c >= 128)) {
            int i = cc >> 1;
            float fl = (float)(i >> 1);
            float dimt = exp2f(fl * 0.415241011861f);
            float arg = (float)(h + 1) * (6.2831853071795864769f / (64.f + 1e-6f)) / dimt;
            v = (cc & 1) ? __cosf(arg) : __sinf(arg);
        }
        wsplit(g_vals + idx, g_vals + S_VAL + idx, v);
        return;
    }
    bb -= B1;
    if (bb < B2) {
        int idx = bb * 256 + tid;
        int o = idx / KP1;
        int rr = idx % KP1;
        float v = w_sm[(o * D + (rr & 255)) * 9 + (rr >> 8)];
        wsplit(g_wts + idx, g_wts + S_WT + idx, v);
        return;
    }
    bb -= B2;
    if (bb < B3) {
        int idx = bb * 256 + tid;
        int l = idx / (512 * D);
        int rr = idx % (512 * D);
        int n = rr >> 8;
        int k = rr & 255;
        float v = (n < 256) ? w_b1[n * 256 + k] : w_r1[(n - 256) * 256 + k];
        long long o = (long long)l * 768 * 256 + (long long)n * 256 + k;
        wsplit(g_wbigs + o, g_wbigs + S_WBIG + o, v);
        return;
    }
    bb -= B3;
    if (bb < B3B) {
        int idx = bb * 256 + tid;
        int l = idx / 512, n = idx % 512;
        g_bbig[l * 768 + n] = (n < 256) ? b_b1[n] : b_r1[n - 256];
        return;
    }
    bb -= B3B;
    if (bb < B4) {
        long long i = (long long)bb * 256 + tid;
        if (i < S_WP1) { wsplit(g_Wp1s + i, g_Wp1s + S_WP1 + i, Wp1[i]); return; }
        i -= S_WP1;
        if (i < S_WLAT) wsplit(g_wlats + i, g_wlats + S_WLAT + i, w_lat[i]);
        return;
    }
    bb -= B4;
    if (bb < B5) {
        int z = bb / 64;
        int rem = bb % 64;
        int l = z >> 1;
        int mode = z & 1;
        int c0 = (rem & 7) * 32, r0 = (rem >> 3) * 32;
        int tx = tid & 31, ty = tid >> 5;
        const float* P = Wp2 + (long long)l * 65536;
        float acc[4] = {};
        for (int ko = 0; ko < 256; ko += 32) {
#pragma unroll
            for (int t = 0; t < 4; t++) {
                int i = ty * 4 + t;
                Bs[i][tx] = P[(ko + i) * 256 + c0 + tx];
                if (mode == 0) As[i][tx] = Wq[(long long)l * 65536 + (ko + i) * 256 + r0 + tx];
                else           As[tx][i] = Wo[(long long)l * 65536 + (r0 + i) * 256 + ko + tx];
            }
            __syncthreads();
#pragma unroll
            for (int i = 0; i < 32; i++) {
                float bv = Bs[i][tx];
                acc[0] += As[i][ty] * bv;
                acc[1] += As[i][ty + 8] * bv;
                acc[2] += As[i][ty + 16] * bv;
                acc[3] += As[i][ty + 24] * bv;
            }
            __syncthreads();
        }
#pragma unroll
        for (int e = 0; e < 4; e++) {
            int row = r0 + ty + 8 * e;
            int col = c0 + tx;
            if (mode == 0) {
                long long o = (long long)l * 768 * 256 + (long long)(512 + col) * 256 + row;
                wsplit(g_wbigs + o, g_wbigs + S_WBIG + o, acc[e]);
            } else {
                g_WoP[(long long)l * 65536 + (long long)row * 256 + col] = acc[e];
            }
        }
        return;
    }
    bb -= B5;
    if (bb < B6) {
        float* vec = &Bs[0][0];
        float* loc = &As[0][0];
        int t = tid;
        if (bb == 2 * NLAY) {
            float a = b_in[t];
            for (int c = 0; c < 128; c++) a += w_in[t * 128 + c] * b_tf[c];
            loc[t] = a;
            __syncthreads();
            float s = b_lat[t];
            for (int c = 0; c < 256; c++) s += w_lat[t * 256 + c] * loc[c];
            g_b2v[t] = s;
            return;
        }
        int l = bb >> 1;
        if ((bb & 1) == 0) {
            vec[t] = bq[l * 256 + t];
            __syncthreads();
            float s = 0.f;
            for (int o = 0; o < 256; o++) s += Wp2[(long long)l * 65536 + o * 256 + t] * vec[o];
            g_bbig[l * 768 + 512 + t] = s;
        } else {
            vec[t] = bp2[l * 256 + t];
            __syncthreads();
            float s = bo[l * 256 + t];
            for (int o = 0; o < 256; o++) s += Wo[(long long)l * 65536 + t * 256 + o] * vec[o];
            g_bo2[l * 256 + t] = s;
        }
        return;
    }
    bb -= B6;
    if (bb < B7) {
        int idx = bb * 256 + tid;
        if (idx < 2 * NQ * D) {
            int qd = idx % (NQ * D);
            float v = qe[qd] + qp[qd];
            g_q[idx] = v;
            wsplit(g_qs + idx, g_qs + S_Q + idx, v);
        }
        if (idx < 2 * NQ * 4) g_boxes[idx] = pbi[idx];
        return;
    }
    bb -= B7;
    {   // transpose feat [b][512][4096] -> split planes [b*4096][512]
        int x = bb & 127, y = (bb >> 7) & 15, b = bb >> 11;
        int hw0 = x * 32, k0 = y * 32;
        const float* src = feat + (long long)b * 512 * HW;
        int tx = tid & 31, ty = tid >> 5;
#pragma unroll
        for (int j = 0; j < 4; j++)
            As[ty + j * 8][tx] = src[(long long)(k0 + ty + j * 8) * HW + hw0 + tx];
        __syncthreads();
#pragma unroll
        for (int j = 0; j < 4; j++) {
            long long o = (long long)(b * HW + hw0 + ty + j * 8) * 512 + k0 + tx;
            wsplit(g_xins + o, g_xins + S_XIN + o, As[tx][ty + j * 8]);
        }
    }
}

// ---------------- fused boxupd + roref + bilinear sample (R14) ----------------
__global__ void rorefsample(const float* __restrict__ w_r2, const float* __restrict__ b_r2,
                            const float* __restrict__ w_b2, const float* __restrict__ b_b2,
                            int do_box) {
    int bq = blockIdx.x;
    int tid = threadIdx.x;
    int warp = tid >> 5, lane = tid & 31;
    __shared__ float h1row[256], hbrow[256], ro[16], refs[16], boxsh[2];
    __shared__ int   soff[72][4];
    __shared__ float swgt[72][4];
    h1row[tid] = g_big[bq * 768 + 256 + tid];
    if (do_box) hbrow[tid] = g_big[bq * 768 + tid];
    else if (tid < 2) boxsh[tid] = g_boxes[bq * 4 + tid];
    __syncthreads();
    if (do_box && warp < 4) {
        float s = 0.f;
        for (int k = lane; k < 256; k += 32) s += hbrow[k] * w_b2[warp * 256 + k];
#pragma unroll
        for (int o = 16; o; o >>= 1) s += __shfl_xor_sync(0xffffffffu, s, o);
        if (lane == 0) {
            float delta = 1.f / (1.f + expf(-(s + b_b2[warp])));
            float nb = g_boxes[bq * 4 + warp] + 0.1f * tanhf(delta - 0.5f);
            nb = fminf(fmaxf(nb, 0.f), 1.f);
            g_boxes[bq * 4 + warp] = nb;
            if (warp < 2) boxsh[warp] = nb;
        }
    }
#pragma unroll
    for (int jj = 0; jj < 2; jj++) {
        int j = warp * 2 + jj;
        float s = 0.f;
        for (int k = lane; k < 256; k += 32) s += h1row[k] * w_r2[j * 256 + k];
#pragma unroll
        for (int o = 16; o; o >>= 1) s += __shfl_xor_sync(0xffffffffu, s, o);
        if (lane == 0) ro[j] = tanhf(s + b_r2[j]);
    }
    __syncthreads();
    if (tid < 8) {
        refs[2 * tid + 0] = fminf(fmaxf(boxsh[0] + 0.5f * ro[2 * tid + 0], 0.f), 1.f);
        refs[2 * tid + 1] = fminf(fmaxf(boxsh[1] + 0.5f * ro[2 * tid + 1], 0.f), 1.f);
    }
    __syncthreads();
    if (tid < 72) {
        int p = tid / 9, tap = tid % 9;
        int cy = tap / 3, cx = tap % 3;
        float ry = refs[2 * p + 1], rx = refs[2 * p];
        float gy = ry * 2.f - 1.f + (float)(cy - 1) * (2.f / 64.f);
        float yy = fminf(fmaxf((gy + 1.f) * 0.5f * 63.f, 0.f), 63.f);
        float y0f = floorf(yy);
        int y0 = (int)y0f;
        float wy = yy - y0f;
        int y1 = min(y0 + 1, 63);
        float gx = rx * 2.f - 1.f + (float)(cx - 1) * (2.f / 64.f);
        float xx = fminf(fmaxf((gx + 1.f) * 0.5f * 63.f, 0.f), 63.f);
        float x0f = floorf(xx);
        int x0 = (int)x0f;
        float wx = xx - x0f;
        int x1 = min(x0 + 1, 63);
        soff[tid][0] = ((y0 << 6) + x0) << 7;
        soff[tid][1] = ((y0 << 6) + x1) << 7;
        soff[tid][2] = ((y1 << 6) + x0) << 7;
        soff[tid][3] = ((y1 << 6) + x1) << 7;
        swgt[tid][0] = (1.f - wx) * (1.f - wy);
        swgt[tid][1] = wx * (1.f - wy);
        swgt[tid][2] = (1.f - wx) * wy;
        swgt[tid][3] = wx * wy;
    }
    __syncthreads();
    int b = bq / NQ;
    const float2* f2 = (const float2*)(g_f0 + (long long)b * HW * D);
    long long qbase = (long long)bq * NP * KP1;
#pragma unroll
    for (int it = 0; it < 36; it++) {
        int idx = tid + it * 256;
        int t72 = idx >> 7, c2 = idx & 127;
        float w00 = swgt[t72][0], w01 = swgt[t72][1], w10 = swgt[t72][2], w11 = swgt[t72][3];
        float2 v00 = f2[soff[t72][0] + c2];
        float2 v01 = f2[soff[t72][1] + c2];
        float2 v10 = f2[soff[t72][2] + c2];
        float2 v11 = f2[soff[t72][3] + c2];
        float vx = v00.x * w00 + v01.x * w01 + v10.x * w10 + v11.x * w11;
        float vy = v00.y * w00 + v01.y * w01 + v10.y * w10 + v11.y * w11;
        int p = t72 / 9, tap = t72 % 9;
        long long o = qbase + (long long)p * KP1 + tap * 256 + 2 * c2;
        bf16 hx = __float2bfloat16(vx), hy = __float2bfloat16(vy);
        *(uint32_t*)(g_flats + o) = pack2(vx, vy);
        float rxl = vx - __bfloat162float(hx), ryl = vy - __bfloat162float(hy);
        *(uint32_t*)(g_flats + S_FLAT + o) = pack2(rxl, ryl);
    }
}

// ---------------- fused attention (online softmax, 32-key tiles) + Wo projection ----------------
__global__ void attn_kernel(const float* __restrict__ WoP, const float* __restrict__ bo2) {
    __shared__ float qs[8][260];
    __shared__ float kvs[32][264];
    __shared__ float tr[8][1056];
    int b = blockIdx.y, qt = blockIdx.x;
    int tid = threadIdx.x;
    int warp = tid >> 5, lane = tid & 31;
    const float* kvb = g_kv + (long long)b * NQ * D;
#pragma unroll
    for (int i = 0; i < 8; i++) {
        int idx = tid + i * 256;
        int qi = idx >> 8, c = idx & 255;
        int q = qt * 8 + qi;
        qs[qi][c] = (q < NQ) ? g_big[((long long)b * NQ + q) * 768 + 512 + c] : 0.f;
    }
    float m_run = -1e30f, s_run = 0.f;
    float out[8] = {};
#pragma unroll
    for (int kt = 0; kt < 10; kt++) {
        __syncthreads();
#pragma unroll
        for (int i = 0; i < 8; i++) {
            int lin = tid + i * 256;
            int j = lin >> 6, c4 = (lin & 63) * 4;
            int key = kt * 32 + j;
            float4 v = make_float4(0.f, 0.f, 0.f, 0.f);
            if (key < NQ) v = *(const float4*)(kvb + (long long)key * D + c4);
            kvs[j][c4] = v.x; kvs[j][c4 + 1] = v.y; kvs[j][c4 + 2] = v.z; kvs[j][c4 + 3] = v.w;
        }
        __syncthreads();
        float p[32] = {};
#pragma unroll
        for (int i = 0; i < 8; i++) {
            float qv = qs[warp][i * 32 + lane];
#pragma unroll
            for (int j = 0; j < 32; j++) p[j] += qv * kvs[j][i * 32 + lane];
        }
#pragma unroll
        for (int j = 0; j < 32; j++) tr[warp][j * 33 + lane] = p[j];
        __syncwarp();
        float s = 0.f;
#pragma unroll
        for (int x = 0; x < 32; x++) s += tr[warp][lane * 33 + x];
        float sc = (kt * 32 + lane < NQ) ? s * 0.0625f : -1e30f;
        float tmax = sc;
#pragma unroll
        for (int o = 16; o; o >>= 1) tmax = fmaxf(tmax, __shfl_xor_sync(0xffffffffu, tmax, o));
        float mnew = fmaxf(m_run, tmax);
        float scale = expf(m_run - mnew);
        float e = expf(sc - mnew);
        float tsum = e;
#pragma unroll
        for (int o = 16; o; o >>= 1) tsum += __shfl_xor_sync(0xffffffffu, tsum, o);
        s_run = s_run * scale + tsum;
        m_run = mnew;
        tr[warp][1024 + lane] = e;
        __syncwarp();
#pragma unroll
        for (int i = 0; i < 8; i++) out[i] *= scale;
#pragma unroll
        for (int j = 0; j < 32; j++) {
            float a = tr[warp][1024 + j];
#pragma unroll
            for (int i = 0; i < 8; i++) out[i] += a * kvs[j][i * 32 + lane];
        }
    }
    float inv = 1.f / s_run;
#pragma unroll
    for (int i = 0; i < 8; i++) out[i] *= inv;
    __syncthreads();
#pragma unroll
    for (int i = 0; i < 8; i++) qs[warp][i * 32 + lane] = out[i];
    float dq[8] = {};
#pragma unroll
    for (int kt = 0; kt < 8; kt++) {
        __syncthreads();
#pragma unroll
        for (int i = 0; i < 8; i++) {
            int lin = tid + i * 256;
            int n = lin >> 3, qd = lin & 7;
            float4 v = *(const float4*)(WoP + (long long)n * 256 + kt * 32 + qd * 4);
            kvs[qd * 4 + 0][n] = v.x;
            kvs[qd * 4 + 1][n] = v.y;
            kvs[qd * 4 + 2][n] = v.z;
            kvs[qd * 4 + 3][n] = v.w;
        }
        __syncthreads();
#pragma unroll
        for (int k = 0; k < 32; k++) {
            float a = qs[warp][kt * 32 + k];
#pragma unroll
            for (int j = 0; j < 8; j++) dq[j] += a * kvs[k][lane + j * 32];
        }
    }
    int q = qt * 8 + warp;
    if (q < NQ) {
#pragma unroll
        for (int j = 0; j < 8; j++) {
            int n = lane + j * 32;
            long long o = ((long long)b * NQ + q) * D + n;
            float v = g_q[o] + dq[j] + bo2[n];
            g_q[o] = v;
            wsplit(g_qs + o, g_qs + S_Q + o, v);
        }
    }
}

// ---------------- final: last boxupd + cls + box copy ----------------
__global__ void final_kernel(const float* __restrict__ w_b2, const float* __restrict__ b_b2,
                             const float* __restrict__ w_cls, const float* __restrict__ b_cls,
                             float* __restrict__ out) {
    int bq = blockIdx.x;
    int tid = threadIdx.x;
    int warp = tid >> 5, lane = tid & 31;
    __shared__ float hrow[256];
    hrow[tid] = g_big[bq * 768 + tid];
    hrow[tid + 128] = g_big[bq * 768 + 128 + tid];
    __syncthreads();
    float s = 0.f;
    for (int k = lane; k < 256; k += 32) s += hrow[k] * w_b2[warp * 256 + k];
#pragma unroll
    for (int o = 16; o; o >>= 1) s += __shfl_xor_sync(0xffffffffu, s, o);
    if (lane == 0) {
        float delta = 1.f / (1.f + expf(-(s + b_b2[warp])));
        float nb = g_boxes[bq * 4 + warp] + 0.1f * tanhf(delta - 0.5f);
        out[600 + bq * 4 + warp] = fminf(fmaxf(nb, 0.f), 1.f);
    }
    if (warp == 0) {
        float s2 = 0.f;
        for (int k = lane; k < 256; k += 32) s2 += g_q[bq * 256 + k] * w_cls[k];
#pragma unroll
        for (int o = 16; o; o >>= 1) s2 += __shfl_xor_sync(0xffffffffu, s2, o);
        if (lane == 0) out[bq] = s2 + b_cls[0];
    }
}

// ---------------- host ----------------
static GD mkgd(const bf16* A, long long sA, const bf16* W, long long sW,
               const float* bias, float* C, int ldc, bf16* OS, long long sOS,
               int M, int N, int K, int act, int accum, int mode, int pos, int epi) {
    GD d;
    d.A = A; d.sA = sA; d.W = W; d.sW = sW; d.bias = bias; d.C = C; d.ldc = ldc;
    d.OS = OS; d.sOS = sOS; d.M = M; d.N = N; d.K = K; d.act = act; d.accum = accum;
    d.mode = mode; d.pos = pos; d.epi = epi;
    return d;
}
static void gemm3(int MT, const GD& d) {
    dim3 grid((d.M + MT - 1) / MT, (d.N + 63) / 64);
    if (MT == 128) tc_gemm3<128, 4><<<grid, 256>>>(d);
    else           tc_gemm3<64, 5><<<grid, 256>>>(d);
}

extern "C" void kernel_launch(void* const* d_in, const int* in_sizes, int n_in,
                              void* d_out, int out_size) {
    const float* feat   = (const float*)d_in[0];
    const float* pbi    = (const float*)d_in[1];
    const float* w_tf   = (const float*)d_in[2];
    const float* b_tf   = (const float*)d_in[3];
    const float* w_in   = (const float*)d_in[4];
    const float* b_in   = (const float*)d_in[5];
    const float* w_lat  = (const float*)d_in[6];
    const float* b_lat  = (const float*)d_in[7];
    const float* w_sm   = (const float*)d_in[8];
    const float* b_sm   = (const float*)d_in[9];
    const float* q_embed= (const float*)d_in[10];
    const float* q_pos  = (const float*)d_in[11];
    const float* Wq     = (const float*)d_in[12];
    const float* bqv    = (const float*)d_in[13];
    const float* Wo     = (const float*)d_in[14];
    const float* bo     = (const float*)d_in[15];
    const float* Wp1    = (const float*)d_in[16];
    const float* bp1    = (const float*)d_in[17];
    const float* Wp2    = (const float*)d_in[18];
    const float* bp2    = (const float*)d_in[19];
    const float* w_r1   = (const float*)d_in[20];
    const float* b_r1   = (const float*)d_in[21];
    const float* w_r2   = (const float*)d_in[22];
    const float* b_r2   = (const float*)d_in[23];
    const float* w_b1   = (const float*)d_in[24];
    const float* b_b1   = (const float*)d_in[25];
    const float* w_b2   = (const float*)d_in[26];
    const float* b_b2   = (const float*)d_in[27];
    const float* w_cls  = (const float*)d_in[28];
    const float* b_cls  = (const float*)d_in[29];
    float* out = (float*)d_out;

    float *p_bbig, *p_bo2, *p_f0, *p_kv, *p_q, *p_big, *p_pos, *p_WoP;
    bf16 *p_coeffs, *p_w_ins, *p_vals, *p_WcTs, *p_wlats, *p_W2s, *p_wts, *p_Wp1s, *p_wbigs;
    bf16 *p_xins, *p_ys, *p_flats, *p_qs;
    cudaGetSymbolAddress((void**)&p_bbig, g_bbig);
    cudaGetSymbolAddress((void**)&p_bo2, g_bo2);
    cudaGetSymbolAddress((void**)&p_f0, g_f0);
    cudaGetSymbolAddress((void**)&p_kv, g_kv);
    cudaGetSymbolAddress((void**)&p_q, g_q);
    cudaGetSymbolAddress((void**)&p_big, g_big);
    cudaGetSymbolAddress((void**)&p_pos, g_pos);
    cudaGetSymbolAddress((void**)&p_WoP, g_WoP);
    cudaGetSymbolAddress((void**)&p_coeffs, g_coeffs);
    cudaGetSymbolAddress((void**)&p_w_ins, g_w_ins);
    cudaGetSymbolAddress((void**)&p_vals, g_vals);
    cudaGetSymbolAddress((void**)&p_WcTs, g_WcTs);
    cudaGetSymbolAddress((void**)&p_wlats, g_wlats);
    cudaGetSymbolAddress((void**)&p_W2s, g_W2s);
    cudaGetSymbolAddress((void**)&p_wts, g_wts);
    cudaGetSymbolAddress((void**)&p_Wp1s, g_Wp1s);
    cudaGetSymbolAddress((void**)&p_wbigs, g_wbigs);
    cudaGetSymbolAddress((void**)&p_xins, g_xins);
    cudaGetSymbolAddress((void**)&p_ys, g_ys);
    cudaGetSymbolAddress((void**)&p_flats, g_flats);
    cudaGetSymbolAddress((void**)&p_qs, g_qs);

    // ---- prep (includes transpose) ----
    megaprep<<<NBLK, 256>>>(w_tf, b_tf, w_in, b_in, w_sm, w_b1, b_b1, w_r1, b_r1,
                            Wp1, w_lat, Wp2, Wq, Wo, bqv, bp2, bo, b_lat,
                            q_embed, q_pos, pbi, feat);
    // batched independent small GEMMs: preloop, WcT, pos-tables
    {
        GD d0 = mkgd(p_qs, S_Q, p_wbigs + 256 * 256, S_WBIG, p_bbig + 256, p_big + 256, 768,
                     nullptr, 0, 2 * NQ, 512, 256, 3, 0, 0, 0, 0);
        GD d1 = mkgd(p_coeffs, S_COEF, p_w_ins, S_WIN, nullptr, nullptr, 256, p_WcTs, S_WCT,
                     512, 256, 128, 0, 0, 0, 0, 3);
        GD d2 = mkgd(p_vals, S_VAL, p_wlats, S_WLAT, nullptr, p_pos, 256, nullptr, 0,
                     128, 256, 256, 0, 0, 0, 0, 0);
        tc_gemm3_b3<64, 5><<<dim3(10, 8, 3), 256>>>(d0, d1, d2);
    }
    // W2 = w_lat @ WcT^T
    gemm3(64, mkgd(p_wlats, S_WLAT, p_WcTs, S_WCT, nullptr, nullptr, 512, p_W2s, S_W2,
                   256, 512, 256, 0, 0, 0, 0, 3));

    // ---- backbone ----
    gemm3(128, mkgd(p_xins, S_XIN, p_W2s, S_W2, nullptr, nullptr, 256, p_ys, S_Y,
                    2 * HW, 256, 512, 0, 0, 0, 1, 3));
    gemm3(128, mkgd(p_ys, S_Y, p_wts, S_WT, b_sm, p_f0, 256, nullptr, 0,
                    2 * HW, 256, KP1, 0, 0, 1, 0, 0));

    for (int l = 0; l < NLAY; l++) {
        rorefsample<<<2 * NQ, 256>>>(w_r2, b_r2, w_b2, b_b2, l > 0);
        gemm3(128, mkgd(p_flats, S_FLAT, p_Wp1s + (long long)l * 256 * KP1, S_WP1, bp1 + l * D,
                        p_kv, 256, nullptr, 0, 2 * NQ * NP, 256, KP1, 0, 0, 0, 0, 1));
        attn_kernel<<<dim3(38, 2), 256>>>(p_WoP + (long long)l * 65536, p_bo2 + l * 256);
        if (l < NLAY - 1) {
            gemm3(64, mkgd(p_qs, S_Q, p_wbigs + (long long)(l + 1) * 768 * 256, S_WBIG,
                           p_bbig + (l + 1) * 768, p_big, 768, nullptr, 0,
                           2 * NQ, 768, 256, 2, 0, 0, 0, 0));
        } else {
            gemm3(64, mkgd(p_qs, S_Q, p_wbigs, S_WBIG, p_bbig, p_big, 768, nullptr, 0,
                           2 * NQ, 256, 256, 1, 0, 0, 0, 0));
        }
    }

    final_kernel<<<2 * NQ, 128>>>(w_b2, b_b2, w_cls, b_cls, out);
}

// round 16
// speedup vs baseline: 1.5098x; 1.5098x over previous
#include <cuda_runtime.h>
#include <cuda_bf16.h>
#include <math.h>
#include <stdint.h>

#define D 256
#define HW 4096
#define NQ 300
#define NP 8
#define KP1 2304
#define NLAY 6

typedef __nv_bfloat16 bf16;

// plane strides
#define S_XIN ((long long)2 * HW * 512)
#define S_Y   ((long long)2 * HW * 256)
#define S_FLAT ((long long)2 * NQ * NP * KP1)
#define S_Q   ((long long)2 * NQ * 256)
#define S_W2  ((long long)256 * 512)
#define S_WT  ((long long)256 * KP1)
#define S_WP1 ((long long)NLAY * 256 * KP1)
#define S_WBIG ((long long)NLAY * 768 * 256)
#define S_WCT ((long long)512 * 256)
#define S_WLAT ((long long)256 * 256)
#define S_COEF ((long long)512 * 128)
#define S_WIN  ((long long)256 * 128)
#define S_VAL  ((long long)128 * 256)

// ---------------- scratch (device globals; no allocation) ----------------
__device__ float g_b2v[D];
__device__ float g_pos[128 * 256];
__device__ float g_bbig[NLAY * 768];
__device__ float g_bo2[NLAY * 256];
__device__ float g_WoP[NLAY * 256 * 256];
__device__ bf16 g_coeffs[2 * S_COEF];
__device__ bf16 g_w_ins[2 * S_WIN];
__device__ bf16 g_vals[2 * S_VAL];
__device__ bf16 g_WcTs[2 * S_WCT];
__device__ bf16 g_wlats[2 * S_WLAT];
__device__ bf16 g_W2s[2 * S_W2];
__device__ bf16 g_wts[2 * S_WT];
__device__ bf16 g_Wp1s[2 * S_WP1];
__device__ bf16 g_wbigs[2 * S_WBIG];
__device__ bf16 g_xins[2 * S_XIN];
__device__ bf16 g_ys[2 * S_Y];
__device__ bf16 g_flats[2 * S_FLAT];
__device__ bf16 g_qs[2 * S_Q];
__device__ float g_f0[2 * HW * D];
__device__ float g_q[2 * NQ * D];
__device__ float g_big[2 * NQ * 768];
__device__ float g_kv[2 * NQ * D];
__device__ float g_boxes[2 * NQ * 4];

__device__ __forceinline__ void wsplit(bf16* h, bf16* l, float v) {
    bf16 hh = __float2bfloat16(v);
    *h = hh;
    *l = __float2bfloat16(v - __bfloat162float(hh));
}
__device__ __forceinline__ uint32_t pack2(float x, float y) {
    __nv_bfloat162 t = __floats2bfloat162_rn(x, y);
    return *(uint32_t*)&t;
}

__device__ __forceinline__ void mma_bf16(float* c, const uint32_t* a, const uint32_t* b) {
    asm volatile(
        "mma.sync.aligned.m16n8k16.row.col.f32.bf16.bf16.f32 "
        "{%0,%1,%2,%3},{%4,%5,%6,%7},{%8,%9},{%0,%1,%2,%3};"
        : "+f"(c[0]), "+f"(c[1]), "+f"(c[2]), "+f"(c[3])
        : "r"(a[0]), "r"(a[1]), "r"(a[2]), "r"(a[3]), "r"(b[0]), "r"(b[1]));
}

__device__ __forceinline__ void ldm4(uint32_t* r, const void* p) {
    uint32_t a = (uint32_t)__cvta_generic_to_shared(p);
    asm volatile("ldmatrix.sync.aligned.m8n8.x4.shared.b16 {%0,%1,%2,%3}, [%4];"
                 : "=r"(r[0]), "=r"(r[1]), "=r"(r[2]), "=r"(r[3]) : "r"(a));
}

__device__ __forceinline__ void cp16(void* dst, const void* src, int bytes) {
    uint32_t d = (uint32_t)__cvta_generic_to_shared(dst);
    asm volatile("cp.async.ca.shared.global [%0], [%1], 16, %2;\n" ::"r"(d), "l"(src), "r"(bytes));
}
__device__ __forceinline__ void cp_commit() { asm volatile("cp.async.commit_group;\n"); }
template <int N>
__device__ __forceinline__ void cp_waitN() { asm volatile("cp.async.wait_group %0;\n" ::"n"(N)); }

// ---------------- GEMM descriptor + shared body ----------------
struct GD {
    const bf16* A; long long sA;
    const bf16* W; long long sW;
    const float* bias; float* C; int ldc;
    bf16* OS; long long sOS;
    int M, N, K, act, accum, mode, pos, epi;
};

template <int MT, int NS>
__device__ __forceinline__ void gemm_body(const GD& d, int bx, int by) {
    constexpr int MSUB = MT / 4;
    constexpr int NMT = MT / 64;
    __shared__ uint32_t sAh[NS][MT][12], sAl[NS][MT][12];
    __shared__ uint32_t sBh[NS][64][12], sBl[NS][64][12];
    int m0 = bx * MT, n0 = by * 64;
    int tid = threadIdx.x;
    int warp = tid >> 5, lane = tid & 31;
    int wm = warp >> 1, wn = warp & 1;
    int g = lane >> 2, r = lane & 3;
    int lrow = lane & 15, lcol = (lane >> 4) * 4;
    float acc[NMT][4][4] = {};
    int nk = d.K >> 4;

    auto load = [&](int s, int k0) {
        if (MT == 128) {
            int row = tid >> 1, ch = tid & 1;
            int m = m0 + row;
            long long off = 0;
            int bytes = 0;
            if (d.mode == 0) {
                if (m < d.M) { off = (long long)m * d.K + k0 + ch * 8; bytes = 16; }
            } else {
                int tap = k0 >> 8;
                int dy = tap / 3 - 1, dx = tap % 3 - 1;
                int h = (m >> 6) & 63, w = m & 63;
                int hh = h + dy, ww = w + dx;
                if (m < d.M && (unsigned)hh < 64u && (unsigned)ww < 64u) {
                    off = (long long)(m + dy * 64 + dx) * 256 + (k0 & 255) + ch * 8;
                    bytes = 16;
                }
            }
            cp16(&sAh[s][row][ch * 4], d.A + off, bytes);
            cp16(&sAl[s][row][ch * 4], d.A + d.sA + off, bytes);
        } else {
            int p = tid >> 7;
            int row = (tid >> 1) & 63, ch = tid & 1;
            int m = m0 + row;
            long long off = 0;
            int bytes = 0;
            if (m < d.M) { off = (long long)m * d.K + k0 + ch * 8; bytes = 16; }
            if (p) cp16(&sAl[s][row][ch * 4], d.A + d.sA + off, bytes);
            else   cp16(&sAh[s][row][ch * 4], d.A + off, bytes);
        }
        {
            int p = tid >> 7;
            int row = (tid >> 1) & 63, ch = tid & 1;
            int n = n0 + row;
            const bf16* src = d.W;
            int bytes = 0;
            if (n < d.N) {
                src = d.W + (long long)p * d.sW + (long long)n * d.K + k0 + ch * 8;
                bytes = 16;
            }
            if (p) cp16(&sBl[s][row][ch * 4], src, bytes);
            else   cp16(&sBh[s][row][ch * 4], src, bytes);
        }
        cp_commit();
    };

#pragma unroll
    for (int s = 0; s < NS - 1; s++) {
        if (s < nk) load(s, s << 4);
        else cp_commit();
    }
    for (int kt = 0; kt < nk; kt++) {
        int cur = kt % NS;
        cp_waitN<NS - 2>();
        __syncthreads();
        if (kt + NS - 1 < nk) load((kt + NS - 1) % NS, (kt + NS - 1) << 4);
        else cp_commit();
        uint32_t ah[NMT][4], al[NMT][4], bh[4][2], bl[4][2];
#pragma unroll
        for (int mt = 0; mt < NMT; mt++) {
            int rb = wm * MSUB + mt * 16;
            ldm4(ah[mt], &sAh[cur][rb + lrow][lcol]);
            ldm4(al[mt], &sAl[cur][rb + lrow][lcol]);
        }
#pragma unroll
        for (int np = 0; np < 2; np++) {
            int cb = wn * 32 + np * 16;
            uint32_t t[4];
            ldm4(t, &sBh[cur][cb + lrow][lcol]);
            bh[2 * np][0] = t[0]; bh[2 * np + 1][0] = t[1];
            bh[2 * np][1] = t[2]; bh[2 * np + 1][1] = t[3];
            ldm4(t, &sBl[cur][cb + lrow][lcol]);
            bl[2 * np][0] = t[0]; bl[2 * np + 1][0] = t[1];
            bl[2 * np][1] = t[2]; bl[2 * np + 1][1] = t[3];
        }
#pragma unroll
        for (int mt = 0; mt < NMT; mt++)
#pragma unroll
            for (int nt = 0; nt < 4; nt++) {
                mma_bf16(acc[mt][nt], ah[mt], bh[nt]);
                mma_bf16(acc[mt][nt], al[mt], bh[nt]);
                mma_bf16(acc[mt][nt], ah[mt], bl[nt]);
            }
    }

    if (d.epi == 1) {
#pragma unroll
        for (int mt = 0; mt < NMT; mt++) {
            int rbase = m0 + wm * MSUB + mt * 16;
#pragma unroll
            for (int nt = 0; nt < 4; nt++) {
                int n = n0 + wn * 32 + nt * 8 + 2 * r;
#pragma unroll
                for (int e = 0; e < 4; e++) {
                    int nn = n + (e & 1);
                    float v = fmaxf(acc[mt][nt][e] + d.bias[nn], 0.f);
                    v += __shfl_xor_sync(0xffffffffu, v, 4);
                    v += __shfl_xor_sync(0xffffffffu, v, 8);
                    v += __shfl_xor_sync(0xffffffffu, v, 16);
                    if (g == 0) {
                        int q = (rbase >> 3) + ((e >= 2) ? 1 : 0);
                        if (q < 2 * NQ) d.C[(long long)q * 256 + nn] = v * 0.125f;
                    }
                }
            }
        }
        return;
    }
#pragma unroll
    for (int mt = 0; mt < NMT; mt++) {
        int rbase = m0 + wm * MSUB + mt * 16;
#pragma unroll
        for (int nt = 0; nt < 4; nt++) {
            int cbase = n0 + wn * 32 + nt * 8 + 2 * r;
#pragma unroll
            for (int e = 0; e < 4; e++) {
                int m = rbase + g + ((e >= 2) ? 8 : 0);
                int n = cbase + (e & 1);
                if (m < d.M && n < d.N) {
                    float v = acc[mt][nt][e];
                    if (d.bias) v += d.bias[n];
                    if (d.act == 1 || (d.act == 2 && n < 512) || (d.act == 3 && n < 256))
                        v = fmaxf(v, 0.f);
                    if (d.pos) {
                        int hw = m & 4095;
                        v += g_pos[(hw >> 6) * 256 + n] + g_pos[16384 + (hw & 63) * 256 + n]
                           + g_b2v[n];
                    }
                    if (d.epi == 3) {
                        long long o = (long long)m * d.N + n;
                        wsplit(d.OS + o, d.OS + d.sOS + o, v);
                    } else {
                        if (d.accum) v += d.C[(long long)m * d.ldc + n];
                        d.C[(long long)m * d.ldc + n] = v;
                    }
                }
            }
        }
    }
}

template <int MT, int NS>
__global__ void __launch_bounds__(256, 2) tc_gemm3(GD d) {
    gemm_body<MT, NS>(d, blockIdx.x, blockIdx.y);
}

template <int MT, int NS>
__global__ void __launch_bounds__(256, 2) tc_gemm3_b3(GD d0, GD d1, GD d2) {
    GD d = (blockIdx.z == 0) ? d0 : ((blockIdx.z == 1) ? d1 : d2);
    if (blockIdx.x * MT >= d.M || (int)blockIdx.y * 64 >= d.N) return;
    gemm_body<MT, NS>(d, blockIdx.x, blockIdx.y);
}

// ---------------- MEGA-PREP (R14 blocks + transpose merged in) ----------------
#define B0 256
#define B0C 128
#define B1 128
#define B2 2304
#define B3 3072
#define B3B 12
#define B4 14080
#define B5 768
#define B6 13
#define B7 600
#define BT 4096
#define NBLK (B0 + B0C + B1 + B2 + B3 + B3B + B4 + B5 + B6 + B7 + BT)

__global__ void megaprep(
    const float* __restrict__ w_tf, const float* __restrict__ b_tf,
    const float* __restrict__ w_in, const float* __restrict__ b_in,
    const float* __restrict__ w_sm,
    const float* __restrict__ w_b1, const float* __restrict__ b_b1,
    const float* __restrict__ w_r1, const float* __restrict__ b_r1,
    const float* __restrict__ Wp1, const float* __restrict__ w_lat,
    const float* __restrict__ Wp2, const float* __restrict__ Wq,
    const float* __restrict__ Wo,
    const float* __restrict__ bq, const float* __restrict__ bp2,
    const float* __restrict__ bo, const float* __restrict__ b_lat,
    const float* __restrict__ qe, const float* __restrict__ qp,
    const float* __restrict__ pbi, const float* __restrict__ feat) {
    __shared__ float As[32][33], Bs[32][33];
    int bb = blockIdx.x;
    int tid = threadIdx.x;

    if (bb < B0) {
        int idx = bb * 256 + tid;
        int row = idx >> 7, c = idx & 127;
        int s = row >> 7, i = row & 127;
        const float* w3 = w_tf + (c * 128 + i) * 3;
        float coeff;
        if (s == 0)      coeff = w3[0] + w3[1];
        else if (s == 3) coeff = w3[1] + w3[2];
        else             coeff = w3[0] + w3[1] + w3[2];
        wsplit(g_coeffs + idx, g_coeffs + S_COEF + idx, 0.25f * coeff);
        return;
    }
    bb -= B0;
    if (bb < B0C) {
        int idx = bb * 256 + tid;
        wsplit(g_w_ins + idx, g_w_ins + S_WIN + idx, w_in[idx]);
        return;
    }
    bb -= B0C;
    if (bb < B1) {
        int idx = bb * 256 + tid;
        int m = idx >> 8, c = idx & 255;
        float v = 0.f;
        int h = m & 63;
        bool lowhalf = (m < 64);
        int cc = lowhalf ? c : c - 128;
        if ((lowhalf && c < 128) || (!lowhalf && c >= 128)) {
            int i = cc >> 1;
            float fl = (float)(i >> 1);
            float dimt = exp2f(fl * 0.415241011861f);
            float arg = (float)(h + 1) * (6.2831853071795864769f / (64.f + 1e-6f)) / dimt;
            v = (cc & 1) ? __cosf(arg) : __sinf(arg);
        }
        wsplit(g_vals + idx, g_vals + S_VAL + idx, v);
        return;
    }
    bb -= B1;
    if (bb < B2) {
        int idx = bb * 256 + tid;
        int o = idx / KP1;
        int rr = idx % KP1;
        float v = w_sm[(o * D + (rr & 255)) * 9 + (rr >> 8)];
        wsplit(g_wts + idx, g_wts + S_WT + idx, v);
        return;
    }
    bb -= B2;
    if (bb < B3) {
        int idx = bb * 256 + tid;
        int l = idx / (512 * D);
        int rr = idx % (512 * D);
        int n = rr >> 8;
        int k = rr & 255;
        float v = (n < 256) ? w_b1[n * 256 + k] : w_r1[(n - 256) * 256 + k];
        long long o = (long long)l * 768 * 256 + (long long)n * 256 + k;
        wsplit(g_wbigs + o, g_wbigs + S_WBIG + o, v);
        return;
    }
    bb -= B3;
    if (bb < B3B) {
        int idx = bb * 256 + tid;
        int l = idx / 512, n = idx % 512;
        g_bbig[l * 768 + n] = (n < 256) ? b_b1[n] : b_r1[n - 256];
        return;
    }
    bb -= B3B;
    if (bb < B4) {
        long long i = (long long)bb * 256 + tid;
        if (i < S_WP1) { wsplit(g_Wp1s + i, g_Wp1s + S_WP1 + i, Wp1[i]); return; }
        i -= S_WP1;
        if (i < S_WLAT) wsplit(g_wlats + i, g_wlats + S_WLAT + i, w_lat[i]);
        return;
    }
    bb -= B4;
    if (bb < B5) {
        int z = bb / 64;
        int rem = bb % 64;
        int l = z >> 1;
        int mode = z & 1;
        int c0 = (rem & 7) * 32, r0 = (rem >> 3) * 32;
        int tx = tid & 31, ty = tid >> 5;
        const float* P = Wp2 + (long long)l * 65536;
        float acc[4] = {};
        for (int ko = 0; ko < 256; ko += 32) {
#pragma unroll
            for (int t = 0; t < 4; t++) {
                int i = ty * 4 + t;
                Bs[i][tx] = P[(ko + i) * 256 + c0 + tx];
                if (mode == 0) As[i][tx] = Wq[(long long)l * 65536 + (ko + i) * 256 + r0 + tx];
                else           As[tx][i] = Wo[(long long)l * 65536 + (r0 + i) * 256 + ko + tx];
            }
            __syncthreads();
#pragma unroll
            for (int i = 0; i < 32; i++) {
                float bv = Bs[i][tx];
                acc[0] += As[i][ty] * bv;
                acc[1] += As[i][ty + 8] * bv;
                acc[2] += As[i][ty + 16] * bv;
                acc[3] += As[i][ty + 24] * bv;
            }
            __syncthreads();
        }
#pragma unroll
        for (int e = 0; e < 4; e++) {
            int row = r0 + ty + 8 * e;
            int col = c0 + tx;
            if (mode == 0) {
                long long o = (long long)l * 768 * 256 + (long long)(512 + col) * 256 + row;
                wsplit(g_wbigs + o, g_wbigs + S_WBIG + o, acc[e]);
            } else {
                g_WoP[(long long)l * 65536 + (long long)row * 256 + col] = acc[e];
            }
        }
        return;
    }
    bb -= B5;
    if (bb < B6) {
        float* vec = &Bs[0][0];
        float* loc = &As[0][0];
        int t = tid;
        if (bb == 2 * NLAY) {
            float a = b_in[t];
            for (int c = 0; c < 128; c++) a += w_in[t * 128 + c] * b_tf[c];
            loc[t] = a;
            __syncthreads();
            float s = b_lat[t];
            for (int c = 0; c < 256; c++) s += w_lat[t * 256 + c] * loc[c];
            g_b2v[t] = s;
            return;
        }
        int l = bb >> 1;
        if ((bb & 1) == 0) {
            vec[t] = bq[l * 256 + t];
            __syncthreads();
            float s = 0.f;
            for (int o = 0; o < 256; o++) s += Wp2[(long long)l * 65536 + o * 256 + t] * vec[o];
            g_bbig[l * 768 + 512 + t] = s;
        } else {
            vec[t] = bp2[l * 256 + t];
            __syncthreads();
            float s = bo[l * 256 + t];
            for (int o = 0; o < 256; o++) s += Wo[(long long)l * 65536 + t * 256 + o] * vec[o];
            g_bo2[l * 256 + t] = s;
        }
        return;
    }
    bb -= B6;
    if (bb < B7) {
        int idx = bb * 256 + tid;
        if (idx < 2 * NQ * D) {
            int qd = idx % (NQ * D);
            float v = qe[qd] + qp[qd];
            g_q[idx] = v;
            wsplit(g_qs + idx, g_qs + S_Q + idx, v);
        }
        if (idx < 2 * NQ * 4) g_boxes[idx] = pbi[idx];
        return;
    }
    bb -= B7;
    {   // transpose feat [b][512][4096] -> split planes [b*4096][512]
        int x = bb & 127, y = (bb >> 7) & 15, b = bb >> 11;
        int hw0 = x * 32, k0 = y * 32;
        const float* src = feat + (long long)b * 512 * HW;
        int tx = tid & 31, ty = tid >> 5;
#pragma unroll
        for (int j = 0; j < 4; j++)
            As[ty + j * 8][tx] = src[(long long)(k0 + ty + j * 8) * HW + hw0 + tx];
        __syncthreads();
#pragma unroll
        for (int j = 0; j < 4; j++) {
            long long o = (long long)(b * HW + hw0 + ty + j * 8) * 512 + k0 + tx;
            wsplit(g_xins + o, g_xins + S_XIN + o, As[tx][ty + j * 8]);
        }
    }
}

// ---------------- fused boxupd + roref + bilinear sample (R14) ----------------
__global__ void rorefsample(const float* __restrict__ w_r2, const float* __restrict__ b_r2,
                            const float* __restrict__ w_b2, const float* __restrict__ b_b2,
                            int do_box) {
    int bq = blockIdx.x;
    int tid = threadIdx.x;
    int warp = tid >> 5, lane = tid & 31;
    __shared__ float h1row[256], hbrow[256], ro[16], refs[16], boxsh[2];
    __shared__ int   soff[72][4];
    __shared__ float swgt[72][4];
    h1row[tid] = g_big[bq * 768 + 256 + tid];
    if (do_box) hbrow[tid] = g_big[bq * 768 + tid];
    else if (tid < 2) boxsh[tid] = g_boxes[bq * 4 + tid];
    __syncthreads();
    if (do_box && warp < 4) {
        float s = 0.f;
        for (int k = lane; k < 256; k += 32) s += hbrow[k] * w_b2[warp * 256 + k];
#pragma unroll
        for (int o = 16; o; o >>= 1) s += __shfl_xor_sync(0xffffffffu, s, o);
        if (lane == 0) {
            float delta = 1.f / (1.f + expf(-(s + b_b2[warp])));
            float nb = g_boxes[bq * 4 + warp] + 0.1f * tanhf(delta - 0.5f);
            nb = fminf(fmaxf(nb, 0.f), 1.f);
            g_boxes[bq * 4 + warp] = nb;
            if (warp < 2) boxsh[warp] = nb;
        }
    }
#pragma unroll
    for (int jj = 0; jj < 2; jj++) {
        int j = warp * 2 + jj;
        float s = 0.f;
        for (int k = lane; k < 256; k += 32) s += h1row[k] * w_r2[j * 256 + k];
#pragma unroll
        for (int o = 16; o; o >>= 1) s += __shfl_xor_sync(0xffffffffu, s, o);
        if (lane == 0) ro[j] = tanhf(s + b_r2[j]);
    }
    __syncthreads();
    if (tid < 8) {
        refs[2 * tid + 0] = fminf(fmaxf(boxsh[0] + 0.5f * ro[2 * tid + 0], 0.f), 1.f);
        refs[2 * tid + 1] = fminf(fmaxf(boxsh[1] + 0.5f * ro[2 * tid + 1], 0.f), 1.f);
    }
    __syncthreads();
    if (tid < 72) {
        int p = tid / 9, tap = tid % 9;
        int cy = tap / 3, cx = tap % 3;
        float ry = refs[2 * p + 1], rx = refs[2 * p];
        float gy = ry * 2.f - 1.f + (float)(cy - 1) * (2.f / 64.f);
        float yy = fminf(fmaxf((gy + 1.f) * 0.5f * 63.f, 0.f), 63.f);
        float y0f = floorf(yy);
        int y0 = (int)y0f;
        float wy = yy - y0f;
        int y1 = min(y0 + 1, 63);
        float gx = rx * 2.f - 1.f + (float)(cx - 1) * (2.f / 64.f);
        float xx = fminf(fmaxf((gx + 1.f) * 0.5f * 63.f, 0.f), 63.f);
        float x0f = floorf(xx);
        int x0 = (int)x0f;
        float wx = xx - x0f;
        int x1 = min(x0 + 1, 63);
        soff[tid][0] = ((y0 << 6) + x0) << 7;
        soff[tid][1] = ((y0 << 6) + x1) << 7;
        soff[tid][2] = ((y1 << 6) + x0) << 7;
        soff[tid][3] = ((y1 << 6) + x1) << 7;
        swgt[tid][0] = (1.f - wx) * (1.f - wy);
        swgt[tid][1] = wx * (1.f - wy);
        swgt[tid][2] = (1.f - wx) * wy;
        swgt[tid][3] = wx * wy;
    }
    __syncthreads();
    int b = bq / NQ;
    const float2* f2 = (const float2*)(g_f0 + (long long)b * HW * D);
    long long qbase = (long long)bq * NP * KP1;
#pragma unroll
    for (int it = 0; it < 36; it++) {
        int idx = tid + it * 256;
        int t72 = idx >> 7, c2 = idx & 127;
        float w00 = swgt[t72][0], w01 = swgt[t72][1], w10 = swgt[t72][2], w11 = swgt[t72][3];
        float2 v00 = f2[soff[t72][0] + c2];
        float2 v01 = f2[soff[t72][1] + c2];
        float2 v10 = f2[soff[t72][2] + c2];
        float2 v11 = f2[soff[t72][3] + c2];
        float vx = v00.x * w00 + v01.x * w01 + v10.x * w10 + v11.x * w11;
        float vy = v00.y * w00 + v01.y * w01 + v10.y * w10 + v11.y * w11;
        int p = t72 / 9, tap = t72 % 9;
        long long o = qbase + (long long)p * KP1 + tap * 256 + 2 * c2;
        bf16 hx = __float2bfloat16(vx), hy = __float2bfloat16(vy);
        *(uint32_t*)(g_flats + o) = pack2(vx, vy);
        float rxl = vx - __bfloat162float(hx), ryl = vy - __bfloat162float(hy);
        *(uint32_t*)(g_flats + S_FLAT + o) = pack2(rxl, ryl);
    }
}

// ---------------- fused attention (online softmax, 32-key tiles) + Wo projection ----------------
__global__ void attn_kernel(const float* __restrict__ WoP, const float* __restrict__ bo2) {
    __shared__ float qs[8][260];
    __shared__ float kvs[32][264];
    __shared__ float tr[8][1056];
    int b = blockIdx.y, qt = blockIdx.x;
    int tid = threadIdx.x;
    int warp = tid >> 5, lane = tid & 31;
    const float* kvb = g_kv + (long long)b * NQ * D;
#pragma unroll
    for (int i = 0; i < 8; i++) {
        int idx = tid + i * 256;
        int qi = idx >> 8, c = idx & 255;
        int q = qt * 8 + qi;
        qs[qi][c] = (q < NQ) ? g_big[((long long)b * NQ + q) * 768 + 512 + c] : 0.f;
    }
    float m_run = -1e30f, s_run = 0.f;
    float out[8] = {};
#pragma unroll
    for (int kt = 0; kt < 10; kt++) {
        __syncthreads();
#pragma unroll
        for (int i = 0; i < 8; i++) {
            int lin = tid + i * 256;
            int j = lin >> 6, c4 = (lin & 63) * 4;
            int key = kt * 32 + j;
            float4 v = make_float4(0.f, 0.f, 0.f, 0.f);
            if (key < NQ) v = *(const float4*)(kvb + (long long)key * D + c4);
            kvs[j][c4] = v.x; kvs[j][c4 + 1] = v.y; kvs[j][c4 + 2] = v.z; kvs[j][c4 + 3] = v.w;
        }
        __syncthreads();
        float p[32] = {};
#pragma unroll
        for (int i = 0; i < 8; i++) {
            float qv = qs[warp][i * 32 + lane];
#pragma unroll
            for (int j = 0; j < 32; j++) p[j] += qv * kvs[j][i * 32 + lane];
        }
#pragma unroll
        for (int j = 0; j < 32; j++) tr[warp][j * 33 + lane] = p[j];
        __syncwarp();
        float s = 0.f;
#pragma unroll
        for (int x = 0; x < 32; x++) s += tr[warp][lane * 33 + x];
        float sc = (kt * 32 + lane < NQ) ? s * 0.0625f : -1e30f;
        float tmax = sc;
#pragma unroll
        for (int o = 16; o; o >>= 1) tmax = fmaxf(tmax, __shfl_xor_sync(0xffffffffu, tmax, o));
        float mnew = fmaxf(m_run, tmax);
        float scale = expf(m_run - mnew);
        float e = expf(sc - mnew);
        float tsum = e;
#pragma unroll
        for (int o = 16; o; o >>= 1) tsum += __shfl_xor_sync(0xffffffffu, tsum, o);
        s_run = s_run * scale + tsum;
        m_run = mnew;
        tr[warp][1024 + lane] = e;
        __syncwarp();
#pragma unroll
        for (int i = 0; i < 8; i++) out[i] *= scale;
#pragma unroll
        for (int j = 0; j < 32; j++) {
            float a = tr[warp][1024 + j];
#pragma unroll
            for (int i = 0; i < 8; i++) out[i] += a * kvs[j][i * 32 + lane];
        }
    }
    float inv = 1.f / s_run;
#pragma unroll
    for (int i = 0; i < 8; i++) out[i] *= inv;
    __syncthreads();
#pragma unroll
    for (int i = 0; i < 8; i++) qs[warp][i * 32 + lane] = out[i];
    float dq[8] = {};
#pragma unroll
    for (int kt = 0; kt < 8; kt++) {
        __syncthreads();
#pragma unroll
        for (int i = 0; i < 8; i++) {
            int lin = tid + i * 256;
            int n = lin >> 3, qd = lin & 7;
            float4 v = *(const float4*)(WoP + (long long)n * 256 + kt * 32 + qd * 4);
            kvs[qd * 4 + 0][n] = v.x;
            kvs[qd * 4 + 1][n] = v.y;
            kvs[qd * 4 + 2][n] = v.z;
            kvs[qd * 4 + 3][n] = v.w;
        }
        __syncthreads();
#pragma unroll
        for (int k = 0; k < 32; k++) {
            float a = qs[warp][kt * 32 + k];
#pragma unroll
            for (int j = 0; j < 8; j++) dq[j] += a * kvs[k][lane + j * 32];
        }
    }
    int q = qt * 8 + warp;
    if (q < NQ) {
#pragma unroll
        for (int j = 0; j < 8; j++) {
            int n = lane + j * 32;
            long long o = ((long long)b * NQ + q) * D + n;
            float v = g_q[o] + dq[j] + bo2[n];
            g_q[o] = v;
            wsplit(g_qs + o, g_qs + S_Q + o, v);
        }
    }
}

// ---------------- final: last boxupd + cls + box copy ----------------
__global__ void final_kernel(const float* __restrict__ w_b2, const float* __restrict__ b_b2,
                             const float* __restrict__ w_cls, const float* __restrict__ b_cls,
                             float* __restrict__ out) {
    int bq = blockIdx.x;
    int tid = threadIdx.x;
    int warp = tid >> 5, lane = tid & 31;
    __shared__ float hrow[256];
    hrow[tid] = g_big[bq * 768 + tid];
    hrow[tid + 128] = g_big[bq * 768 + 128 + tid];
    __syncthreads();
    float s = 0.f;
    for (int k = lane; k < 256; k += 32) s += hrow[k] * w_b2[warp * 256 + k];
#pragma unroll
    for (int o = 16; o; o >>= 1) s += __shfl_xor_sync(0xffffffffu, s, o);
    if (lane == 0) {
        float delta = 1.f / (1.f + expf(-(s + b_b2[warp])));
        float nb = g_boxes[bq * 4 + warp] + 0.1f * tanhf(delta - 0.5f);
        out[600 + bq * 4 + warp] = fminf(fmaxf(nb, 0.f), 1.f);
    }
    if (warp == 0) {
        float s2 = 0.f;
        for (int k = lane; k < 256; k += 32) s2 += g_q[bq * 256 + k] * w_cls[k];
#pragma unroll
        for (int o = 16; o; o >>= 1) s2 += __shfl_xor_sync(0xffffffffu, s2, o);
        if (lane == 0) out[bq] = s2 + b_cls[0];
    }
}

// ---------------- host ----------------
static GD mkgd(const bf16* A, long long sA, const bf16* W, long long sW,
               const float* bias, float* C, int ldc, bf16* OS, long long sOS,
               int M, int N, int K, int act, int accum, int mode, int pos, int epi) {
    GD d;
    d.A = A; d.sA = sA; d.W = W; d.sW = sW; d.bias = bias; d.C = C; d.ldc = ldc;
    d.OS = OS; d.sOS = sOS; d.M = M; d.N = N; d.K = K; d.act = act; d.accum = accum;
    d.mode = mode; d.pos = pos; d.epi = epi;
    return d;
}
static void gemm3(int MT, const GD& d) {
    dim3 grid((d.M + MT - 1) / MT, (d.N + 63) / 64);
    if (MT == 128) tc_gemm3<128, 4><<<grid, 256>>>(d);
    else           tc_gemm3<64, 5><<<grid, 256>>>(d);
}

extern "C" void kernel_launch(void* const* d_in, const int* in_sizes, int n_in,
                              void* d_out, int out_size) {
    const float* feat   = (const float*)d_in[0];
    const float* pbi    = (const float*)d_in[1];
    const float* w_tf   = (const float*)d_in[2];
    const float* b_tf   = (const float*)d_in[3];
    const float* w_in   = (const float*)d_in[4];
    const float* b_in   = (const float*)d_in[5];
    const float* w_lat  = (const float*)d_in[6];
    const float* b_lat  = (const float*)d_in[7];
    const float* w_sm   = (const float*)d_in[8];
    const float* b_sm   = (const float*)d_in[9];
    const float* q_embed= (const float*)d_in[10];
    const float* q_pos  = (const float*)d_in[11];
    const float* Wq     = (const float*)d_in[12];
    const float* bqv    = (const float*)d_in[13];
    const float* Wo     = (const float*)d_in[14];
    const float* bo     = (const float*)d_in[15];
    const float* Wp1    = (const float*)d_in[16];
    const float* bp1    = (const float*)d_in[17];
    const float* Wp2    = (const float*)d_in[18];
    const float* bp2    = (const float*)d_in[19];
    const float* w_r1   = (const float*)d_in[20];
    const float* b_r1   = (const float*)d_in[21];
    const float* w_r2   = (const float*)d_in[22];
    const float* b_r2   = (const float*)d_in[23];
    const float* w_b1   = (const float*)d_in[24];
    const float* b_b1   = (const float*)d_in[25];
    const float* w_b2   = (const float*)d_in[26];
    const float* b_b2   = (const float*)d_in[27];
    const float* w_cls  = (const float*)d_in[28];
    const float* b_cls  = (const float*)d_in[29];
    float* out = (float*)d_out;

    float *p_bbig, *p_bo2, *p_f0, *p_kv, *p_q, *p_big, *p_pos, *p_WoP;
    bf16 *p_coeffs, *p_w_ins, *p_vals, *p_WcTs, *p_wlats, *p_W2s, *p_wts, *p_Wp1s, *p_wbigs;
    bf16 *p_xins, *p_ys, *p_flats, *p_qs;
    cudaGetSymbolAddress((void**)&p_bbig, g_bbig);
    cudaGetSymbolAddress((void**)&p_bo2, g_bo2);
    cudaGetSymbolAddress((void**)&p_f0, g_f0);
    cudaGetSymbolAddress((void**)&p_kv, g_kv);
    cudaGetSymbolAddress((void**)&p_q, g_q);
    cudaGetSymbolAddress((void**)&p_big, g_big);
    cudaGetSymbolAddress((void**)&p_pos, g_pos);
    cudaGetSymbolAddress((void**)&p_WoP, g_WoP);
    cudaGetSymbolAddress((void**)&p_coeffs, g_coeffs);
    cudaGetSymbolAddress((void**)&p_w_ins, g_w_ins);
    cudaGetSymbolAddress((void**)&p_vals, g_vals);
    cudaGetSymbolAddress((void**)&p_WcTs, g_WcTs);
    cudaGetSymbolAddress((void**)&p_wlats, g_wlats);
    cudaGetSymbolAddress((void**)&p_W2s, g_W2s);
    cudaGetSymbolAddress((void**)&p_wts, g_wts);
    cudaGetSymbolAddress((void**)&p_Wp1s, g_Wp1s);
    cudaGetSymbolAddress((void**)&p_wbigs, g_wbigs);
    cudaGetSymbolAddress((void**)&p_xins, g_xins);
    cudaGetSymbolAddress((void**)&p_ys, g_ys);
    cudaGetSymbolAddress((void**)&p_flats, g_flats);
    cudaGetSymbolAddress((void**)&p_qs, g_qs);

    // ---- prep (includes transpose) ----
    megaprep<<<NBLK, 256>>>(w_tf, b_tf, w_in, b_in, w_sm, w_b1, b_b1, w_r1, b_r1,
                            Wp1, w_lat, Wp2, Wq, Wo, bqv, bp2, bo, b_lat,
                            q_embed, q_pos, pbi, feat);
    // batched independent small GEMMs: preloop, WcT, pos-tables
    {
        GD d0 = mkgd(p_qs, S_Q, p_wbigs + 256 * 256, S_WBIG, p_bbig + 256, p_big + 256, 768,
                     nullptr, 0, 2 * NQ, 512, 256, 3, 0, 0, 0, 0);
        GD d1 = mkgd(p_coeffs, S_COEF, p_w_ins, S_WIN, nullptr, nullptr, 256, p_WcTs, S_WCT,
                     512, 256, 128, 0, 0, 0, 0, 3);
        GD d2 = mkgd(p_vals, S_VAL, p_wlats, S_WLAT, nullptr, p_pos, 256, nullptr, 0,
                     128, 256, 256, 0, 0, 0, 0, 0);
        tc_gemm3_b3<64, 5><<<dim3(10, 8, 3), 256>>>(d0, d1, d2);
    }
    // W2 = w_lat @ WcT^T
    gemm3(64, mkgd(p_wlats, S_WLAT, p_WcTs, S_WCT, nullptr, nullptr, 512, p_W2s, S_W2,
                   256, 512, 256, 0, 0, 0, 0, 3));

    // ---- backbone ----
    gemm3(128, mkgd(p_xins, S_XIN, p_W2s, S_W2, nullptr, nullptr, 256, p_ys, S_Y,
                    2 * HW, 256, 512, 0, 0, 0, 1, 3));
    gemm3(128, mkgd(p_ys, S_Y, p_wts, S_WT, b_sm, p_f0, 256, nullptr, 0,
                    2 * HW, 256, KP1, 0, 0, 1, 0, 0));

    for (int l = 0; l < NLAY; l++) {
        rorefsample<<<2 * NQ, 256>>>(w_r2, b_r2, w_b2, b_b2, l > 0);
        gemm3(128, mkgd(p_flats, S_FLAT, p_Wp1s + (long long)l * 256 * KP1, S_WP1, bp1 + l * D,
                        p_kv, 256, nullptr, 0, 2 * NQ * NP, 256, KP1, 0, 0, 0, 0, 1));
        attn_kernel<<<dim3(38, 2), 256>>>(p_WoP + (long long)l * 65536, p_bo2 + l * 256);
        if (l < NLAY - 1) {
            gemm3(64, mkgd(p_qs, S_Q, p_wbigs + (long long)(l + 1) * 768 * 256, S_WBIG,
                           p_bbig + (l + 1) * 768, p_big, 768, nullptr, 0,
                           2 * NQ, 768, 256, 2, 0, 0, 0, 0));
        } else {
            gemm3(64, mkgd(p_qs, S_Q, p_wbigs, S_WBIG, p_bbig, p_big, 768, nullptr, 0,
                           2 * NQ, 256, 256, 1, 0, 0, 0, 0));
        }
    }

    final_kernel<<<2 * NQ, 128>>>(w_b2, b_b2, w_cls, b_cls, out);
}